// round 4
// baseline (speedup 1.0000x reference)
#include <cuda_runtime.h>
#include <math.h>

#define NN 50000
#define EE 800000
#define PP 3
#define HH 8
#define DD 32
#define HD 256      // H*D
#define FTOT 768    // P*H*D

// ---------------- scratch (static __device__, no allocations) ----------------
__device__ float g_feat[(size_t)NN * FTOT];   // feat[n][p*256 + h*32 + d]
__device__ float g_z   [(size_t)NN * FTOT];   // aggregated messages (pre-ELU)
__device__ float g_el  [(size_t)PP * NN * HH];
__device__ float g_er  [(size_t)PP * NN * HH];
__device__ float g_den [(size_t)PP * NN * HH];
__device__ float g_ebuf[(size_t)PP * EE * HH]; // ex (unnormalized softmax)

__device__ __forceinline__ float elu_f(float x) {
    return x > 0.f ? x : (__expf(x) - 1.f);
}

// ---------------- init: zero z, den ----------------
__global__ void init_kernel() {
    int t = blockIdx.x * blockDim.x + threadIdx.x;
    const int nz4 = NN * FTOT / 4;                    // 9,600,000
    if (t < nz4) ((float4*)g_z)[t] = make_float4(0.f, 0.f, 0.f, 0.f);
    if (t < PP * NN * HH) g_den[t] = 0.f;
}

// =====================================================================
// Shared GEMM body: C(128x64 tile) += A(128xK) * B(Kx64)
// 256 threads, 8x4 accumulators. A is loaded via functor (ELU fusion for
// GEMM2), B row-major [K][ldb].
// =====================================================================

// ---------------- GEMM1: feat = h @ fc_w ----------------
__global__ __launch_bounds__(256) void gemm_feat_kernel(
    const float* __restrict__ A, const float* __restrict__ fcw)
{
    __shared__ float As[16][132];   // padded: kills store-side bank conflicts
    __shared__ float Bs[16][64];
    const int tid = threadIdx.x;
    const int tx = tid & 15;          // col group (4 cols)
    const int ty = tid >> 4;          // row group (8 rows)
    const int rowBase = blockIdx.y * 128;
    const int colBase = blockIdx.x * 64;
    const int p  = colBase >> 8;      // 64-col tile lies inside one p (256|64)
    const int jB = colBase & 255;
    // A-load mapping: 2 float4 per thread, row = tid>>1, kcol = (tid&1)*8
    const int ar = tid >> 1;
    const int ac = (tid & 1) << 3;
    // B-load mapping: 1 float4 per thread
    const int br = tid >> 4;
    const int bc = (tid & 15) << 2;

    float acc[8][4];
#pragma unroll
    for (int i = 0; i < 8; i++)
#pragma unroll
        for (int j = 0; j < 4; j++) acc[i][j] = 0.f;

    for (int k0 = 0; k0 < 128; k0 += 16) {
        int arow = rowBase + ar;
        float4 av0 = make_float4(0.f,0.f,0.f,0.f), av1 = av0;
        if (arow < NN) {
            const float* ap = A + (size_t)arow * 128 + k0 + ac;
            av0 = *(const float4*)ap;
            av1 = *(const float4*)(ap + 4);
        }
        As[ac + 0][ar] = av0.x; As[ac + 1][ar] = av0.y;
        As[ac + 2][ar] = av0.z; As[ac + 3][ar] = av0.w;
        As[ac + 4][ar] = av1.x; As[ac + 5][ar] = av1.y;
        As[ac + 6][ar] = av1.z; As[ac + 7][ar] = av1.w;

        *(float4*)&Bs[br][bc] = *(const float4*)(fcw + (size_t)p * (128 * 256)
                                               + (size_t)(k0 + br) * 256 + jB + bc);
        __syncthreads();
#pragma unroll
        for (int k = 0; k < 16; k++) {
            float4 a0 = *(const float4*)&As[k][ty << 3];
            float4 a1 = *(const float4*)&As[k][(ty << 3) + 4];
            float4 b4 = *(const float4*)&Bs[k][tx << 2];
            float a[8] = {a0.x, a0.y, a0.z, a0.w, a1.x, a1.y, a1.z, a1.w};
            float b[4] = {b4.x, b4.y, b4.z, b4.w};
#pragma unroll
            for (int i = 0; i < 8; i++)
#pragma unroll
                for (int j = 0; j < 4; j++) acc[i][j] += a[i] * b[j];
        }
        __syncthreads();
    }
#pragma unroll
    for (int i = 0; i < 8; i++) {
        int row = rowBase + (ty << 3) + i;
        if (row < NN)
            *(float4*)(g_feat + (size_t)row * FTOT + colBase + (tx << 2)) =
                make_float4(acc[i][0], acc[i][1], acc[i][2], acc[i][3]);
    }
}

// ---------------- el/er: warp per (n,p) ----------------
__global__ __launch_bounds__(256) void elr_kernel(
    const float* __restrict__ al, const float* __restrict__ arr)
{
    int w = (blockIdx.x * blockDim.x + threadIdx.x) >> 5;
    if (w >= NN * PP) return;
    int lane = threadIdx.x & 31;
    int n = w / PP, p = w - n * PP;
    int h = lane >> 2, dq = (lane & 3) << 3;
    const float* f  = g_feat + (size_t)n * FTOT + p * HD + h * DD + dq;
    const float* lp = al  + p * HD + h * DD + dq;
    const float* rp = arr + p * HD + h * DD + dq;
    float sl = 0.f, sr = 0.f;
#pragma unroll
    for (int i = 0; i < 8; i++) { float v = f[i]; sl += v * lp[i]; sr += v * rp[i]; }
    sl += __shfl_xor_sync(0xffffffffu, sl, 1);
    sl += __shfl_xor_sync(0xffffffffu, sl, 2);
    sr += __shfl_xor_sync(0xffffffffu, sr, 1);
    sr += __shfl_xor_sync(0xffffffffu, sr, 2);
    if ((lane & 3) == 0) {
        g_el[((size_t)p * NN + n) * HH + h] = sl;
        g_er[((size_t)p * NN + n) * HH + h] = sr;
    }
}

// ---------------- edge softmax (single pass, no max shift):
//   ex = exp(leaky(el[src]+er[dst])); den[dst] += ex; store ex ----------------
__global__ __launch_bounds__(256) void edge_soft_kernel(const int* __restrict__ ei) {
    int t = blockIdx.x * blockDim.x + threadIdx.x;
    if (t >= PP * EE) return;
    int p = t / EE, e = t - p * EE;
    int src = ei[(size_t)p * 2 * EE + e];
    int dst = ei[(size_t)p * 2 * EE + EE + e];
    const float4* lp = (const float4*)(g_el + ((size_t)p * NN + src) * HH);
    const float4* rp = (const float4*)(g_er + ((size_t)p * NN + dst) * HH);
    float4 l0 = lp[0], l1 = lp[1], r0 = rp[0], r1 = rp[1];
    float v[8] = { l0.x + r0.x, l0.y + r0.y, l0.z + r0.z, l0.w + r0.w,
                   l1.x + r1.x, l1.y + r1.y, l1.z + r1.z, l1.w + r1.w };
#pragma unroll
    for (int i = 0; i < 8; i++) {
        float x = v[i];
        x = x > 0.f ? x : 0.2f * x;        // leaky_relu(0.2)
        v[i] = __expf(x);                  // logits are O(1): no max shift needed
    }
    float* drow = g_den + ((size_t)p * NN + dst) * HH;
    asm volatile("red.global.add.v4.f32 [%0], {%1,%2,%3,%4};"
                 :: "l"(drow), "f"(v[0]), "f"(v[1]), "f"(v[2]), "f"(v[3]) : "memory");
    asm volatile("red.global.add.v4.f32 [%0], {%1,%2,%3,%4};"
                 :: "l"(drow + 4), "f"(v[4]), "f"(v[5]), "f"(v[6]), "f"(v[7]) : "memory");
    float* erow = g_ebuf + ((size_t)(p * EE + e)) * HH;
    *(float4*)erow       = make_float4(v[0], v[1], v[2], v[3]);
    *((float4*)erow + 1) = make_float4(v[4], v[5], v[6], v[7]);
}

// ---------------- edge aggregation: z[dst] += feat[src] * a   (warp per edge) ----------------
__global__ __launch_bounds__(256) void edge_agg_kernel(const int* __restrict__ ei) {
    int w = (blockIdx.x * blockDim.x + threadIdx.x) >> 5;
    if (w >= PP * EE) return;
    int lane = threadIdx.x & 31;
    int p = w / EE, e = w - p * EE;
    int src = ei[(size_t)p * 2 * EE + e];
    int dst = ei[(size_t)p * 2 * EE + EE + e];
    int h = lane >> 2;
    // one lane per 4-lane head-group computes a, then broadcasts
    float a = 0.f;
    if ((lane & 3) == 0) {
        float ex  = g_ebuf[((size_t)(p * EE + e)) * HH + h];
        float den = g_den [((size_t)p * NN + dst) * HH + h];
        a = __fdividef(ex, den);
    }
    a = __shfl_sync(0xffffffffu, a, lane & ~3);
    const float4* fp = (const float4*)(g_feat + (size_t)src * FTOT + p * HD) + lane * 2;
    float4 v0 = fp[0], v1 = fp[1];
    float* zp = g_z + (size_t)dst * FTOT + p * HD + lane * 8;
    asm volatile("red.global.add.v4.f32 [%0], {%1,%2,%3,%4};"
                 :: "l"(zp), "f"(v0.x * a), "f"(v0.y * a), "f"(v0.z * a), "f"(v0.w * a)
                 : "memory");
    asm volatile("red.global.add.v4.f32 [%0], {%1,%2,%3,%4};"
                 :: "l"(zp + 4), "f"(v1.x * a), "f"(v1.y * a), "f"(v1.z * a), "f"(v1.w * a)
                 : "memory");
}

// ---------------- GEMM2: out = elu(z) @ sem_w + sem_b (ELU fused into A load) ----------------
__global__ __launch_bounds__(256) void gemm_out_kernel(
    const float* __restrict__ semw, const float* __restrict__ semb,
    float* __restrict__ out)
{
    __shared__ float As[16][132];
    __shared__ float Bs[16][64];
    const int tid = threadIdx.x;
    const int tx = tid & 15;
    const int ty = tid >> 4;
    const int rowBase = blockIdx.y * 128;
    const int colBase = blockIdx.x * 64;
    const int ar = tid >> 1;
    const int ac = (tid & 1) << 3;
    const int br = tid >> 4;
    const int bc = (tid & 15) << 2;

    float acc[8][4];
#pragma unroll
    for (int i = 0; i < 8; i++)
#pragma unroll
        for (int j = 0; j < 4; j++) acc[i][j] = 0.f;

    for (int k0 = 0; k0 < FTOT; k0 += 16) {
        int arow = rowBase + ar;
        float4 av0 = make_float4(0.f,0.f,0.f,0.f), av1 = av0;
        if (arow < NN) {
            const float* ap = g_z + (size_t)arow * FTOT + k0 + ac;
            float4 z0 = *(const float4*)ap;
            float4 z1 = *(const float4*)(ap + 4);
            av0 = make_float4(elu_f(z0.x), elu_f(z0.y), elu_f(z0.z), elu_f(z0.w));
            av1 = make_float4(elu_f(z1.x), elu_f(z1.y), elu_f(z1.z), elu_f(z1.w));
        }
        As[ac + 0][ar] = av0.x; As[ac + 1][ar] = av0.y;
        As[ac + 2][ar] = av0.z; As[ac + 3][ar] = av0.w;
        As[ac + 4][ar] = av1.x; As[ac + 5][ar] = av1.y;
        As[ac + 6][ar] = av1.z; As[ac + 7][ar] = av1.w;

        *(float4*)&Bs[br][bc] = *(const float4*)(semw + (size_t)(k0 + br) * 128
                                               + colBase + bc);
        __syncthreads();
#pragma unroll
        for (int k = 0; k < 16; k++) {
            float4 a0 = *(const float4*)&As[k][ty << 3];
            float4 a1 = *(const float4*)&As[k][(ty << 3) + 4];
            float4 b4 = *(const float4*)&Bs[k][tx << 2];
            float a[8] = {a0.x, a0.y, a0.z, a0.w, a1.x, a1.y, a1.z, a1.w};
            float b[4] = {b4.x, b4.y, b4.z, b4.w};
#pragma unroll
            for (int i = 0; i < 8; i++)
#pragma unroll
                for (int j = 0; j < 4; j++) acc[i][j] += a[i] * b[j];
        }
        __syncthreads();
    }
#pragma unroll
    for (int i = 0; i < 8; i++) {
        int row = rowBase + (ty << 3) + i;
        if (row < NN) {
            int col = colBase + (tx << 2);
            float4 bb = *(const float4*)(semb + col);
            *(float4*)(out + (size_t)row * 128 + col) =
                make_float4(acc[i][0] + bb.x, acc[i][1] + bb.y,
                            acc[i][2] + bb.z, acc[i][3] + bb.w);
        }
    }
}

// ---------------- launch ----------------
extern "C" void kernel_launch(void* const* d_in, const int* in_sizes, int n_in,
                              void* d_out, int out_size)
{
    const float* h    = (const float*)d_in[0];
    const int*   ei   = (const int*)  d_in[1];
    const float* fcw  = (const float*)d_in[2];
    const float* al   = (const float*)d_in[3];
    const float* arr  = (const float*)d_in[4];
    const float* semw = (const float*)d_in[5];
    const float* semb = (const float*)d_in[6];
    float* out = (float*)d_out;

    // init: covers max(N*768/4, P*N*8) = 9.6M threads
    init_kernel<<<(NN * FTOT / 4 + 255) / 256, 256>>>();

    dim3 g1(FTOT / 64, (NN + 127) / 128);
    gemm_feat_kernel<<<g1, 256>>>(h, fcw);

    elr_kernel<<<(NN * PP * 32 + 255) / 256, 256>>>(al, arr);

    edge_soft_kernel<<<(PP * EE + 255) / 256, 256>>>(ei);
    edge_agg_kernel<<<((size_t)PP * EE * 32 + 255) / 256, 256>>>(ei);

    dim3 g2(128 / 64, (NN + 127) / 128);
    gemm_out_kernel<<<g2, 256>>>(semw, semb, out);
}

// round 14
// speedup vs baseline: 1.0618x; 1.0618x over previous
#include <cuda_runtime.h>
#include <math.h>

#define NN 50000
#define EE 800000
#define PP 3
#define HH 8
#define DD 32
#define HD 256      // H*D
#define FTOT 768    // P*H*D

// ---------------- scratch (static __device__, no allocations) ----------------
__device__ float g_feat[(size_t)NN * FTOT];   // feat[n][p*256 + h*32 + d]
__device__ float g_z   [(size_t)NN * FTOT];   // unnormalized aggregated messages
__device__ float g_el  [(size_t)PP * NN * HH];
__device__ float g_er  [(size_t)PP * NN * HH];
__device__ float g_den [(size_t)PP * NN * HH]; // sum(ex) then 1/sum(ex)

__device__ __forceinline__ float elu_f(float x) {
    return x > 0.f ? x : (__expf(x) - 1.f);
}

// ---------------- init: zero z, den ----------------
__global__ void init_kernel() {
    int t = blockIdx.x * blockDim.x + threadIdx.x;
    const int nz4 = NN * FTOT / 4;                    // 9,600,000
    if (t < nz4) ((float4*)g_z)[t] = make_float4(0.f, 0.f, 0.f, 0.f);
    if (t < PP * NN * HH) g_den[t] = 0.f;
}

// =====================================================================
// GEMM1: feat = h @ fc_w.  C tile 128x128, 256 threads, 8x8 acc
// (2x2 quadrant scheme). Double-buffered: next k-tile LDGs issued
// before the FFMA block so compute covers load latency.
// =====================================================================
__global__ __launch_bounds__(256) void gemm_feat_kernel(
    const float* __restrict__ A, const float* __restrict__ fcw)
{
    __shared__ float As[16][132];   // padded vs. transposed stores
    __shared__ float Bs[16][128];
    const int tid = threadIdx.x;
    const int tx = tid & 15;
    const int ty = tid >> 4;
    const int rowBase = blockIdx.y * 128;
    const int colBase = blockIdx.x * 128;
    const int p  = colBase >> 8;      // 128-col tile lies inside one p (256 = 2*128)
    const int jB = colBase & 255;     // 0 or 128
    const int ar = tid >> 1;
    const int ac = (tid & 1) << 3;
    const int br = tid >> 5;
    const int bc = (tid & 31) << 2;
    const int arow = rowBase + ar;
    const bool aok = arow < NN;
    const float* apBase = A + (size_t)arow * 128 + ac;
    const float* bpBase = fcw + (size_t)p * (128 * 256) + (size_t)br * 256 + jB + bc;

    float acc[8][8];
#pragma unroll
    for (int i = 0; i < 8; i++)
#pragma unroll
        for (int j = 0; j < 8; j++) acc[i][j] = 0.f;

    // prologue: load k0=0 tile into registers
    float4 av0 = make_float4(0.f,0.f,0.f,0.f), av1 = av0;
    if (aok) { av0 = *(const float4*)apBase; av1 = *(const float4*)(apBase + 4); }
    float4 bv0 = *(const float4*)bpBase;
    float4 bv1 = *(const float4*)(bpBase + 8 * 256);

    for (int k0 = 0; k0 < 128; k0 += 16) {
        As[ac + 0][ar] = av0.x; As[ac + 1][ar] = av0.y;
        As[ac + 2][ar] = av0.z; As[ac + 3][ar] = av0.w;
        As[ac + 4][ar] = av1.x; As[ac + 5][ar] = av1.y;
        As[ac + 6][ar] = av1.z; As[ac + 7][ar] = av1.w;
        *(float4*)&Bs[br][bc]     = bv0;
        *(float4*)&Bs[br + 8][bc] = bv1;
        __syncthreads();

        if (k0 + 16 < 128) {   // prefetch next k-tile
            if (aok) {
                av0 = *(const float4*)(apBase + k0 + 16);
                av1 = *(const float4*)(apBase + k0 + 20);
            }
            bv0 = *(const float4*)(bpBase + (size_t)(k0 + 16) * 256);
            bv1 = *(const float4*)(bpBase + (size_t)(k0 + 24) * 256);
        }
#pragma unroll
        for (int k = 0; k < 16; k++) {
            float4 a0 = *(const float4*)&As[k][ty << 2];
            float4 a1 = *(const float4*)&As[k][(ty << 2) + 64];
            float4 b0 = *(const float4*)&Bs[k][tx << 2];
            float4 b1 = *(const float4*)&Bs[k][(tx << 2) + 64];
            float a[8] = {a0.x, a0.y, a0.z, a0.w, a1.x, a1.y, a1.z, a1.w};
            float b[8] = {b0.x, b0.y, b0.z, b0.w, b1.x, b1.y, b1.z, b1.w};
#pragma unroll
            for (int i = 0; i < 8; i++)
#pragma unroll
                for (int j = 0; j < 8; j++) acc[i][j] += a[i] * b[j];
        }
        __syncthreads();
    }
#pragma unroll
    for (int qi = 0; qi < 2; qi++)
#pragma unroll
    for (int i = 0; i < 4; i++) {
        int row = rowBase + (ty << 2) + qi * 64 + i;
        if (row < NN) {
            float* cp = g_feat + (size_t)row * FTOT + colBase;
            *(float4*)(cp + (tx << 2)) =
                make_float4(acc[qi*4+i][0], acc[qi*4+i][1], acc[qi*4+i][2], acc[qi*4+i][3]);
            *(float4*)(cp + (tx << 2) + 64) =
                make_float4(acc[qi*4+i][4], acc[qi*4+i][5], acc[qi*4+i][6], acc[qi*4+i][7]);
        }
    }
}

// ---------------- el/er: warp per (n,p) ----------------
__global__ __launch_bounds__(256) void elr_kernel(
    const float* __restrict__ al, const float* __restrict__ arr)
{
    int w = (blockIdx.x * blockDim.x + threadIdx.x) >> 5;
    if (w >= NN * PP) return;
    int lane = threadIdx.x & 31;
    int n = w / PP, p = w - n * PP;
    int h = lane >> 2, dq = (lane & 3) << 3;
    const float* f  = g_feat + (size_t)n * FTOT + p * HD + h * DD + dq;
    const float* lp = al  + p * HD + h * DD + dq;
    const float* rp = arr + p * HD + h * DD + dq;
    float sl = 0.f, sr = 0.f;
#pragma unroll
    for (int i = 0; i < 8; i++) { float v = f[i]; sl += v * lp[i]; sr += v * rp[i]; }
    sl += __shfl_xor_sync(0xffffffffu, sl, 1);
    sl += __shfl_xor_sync(0xffffffffu, sl, 2);
    sr += __shfl_xor_sync(0xffffffffu, sr, 1);
    sr += __shfl_xor_sync(0xffffffffu, sr, 2);
    if ((lane & 3) == 0) {
        g_el[((size_t)p * NN + n) * HH + h] = sl;
        g_er[((size_t)p * NN + n) * HH + h] = sr;
    }
}

// ---------------- fused edge pass (warp per edge):
//   ex = exp(leaky(el[src]+er[dst]))        (no max shift: logits are O(1))
//   den[dst] += ex;   z[dst] += ex * feat[src]   (normalization deferred) ----------------
__global__ __launch_bounds__(256) void edge_fused_kernel(const int* __restrict__ ei) {
    int w = (blockIdx.x * blockDim.x + threadIdx.x) >> 5;
    if (w >= PP * EE) return;
    int lane = threadIdx.x & 31;
    int p = w / EE, e = w - p * EE;
    int src = ei[(size_t)p * 2 * EE + e];
    int dst = ei[(size_t)p * 2 * EE + EE + e];
    float ex = 0.f;
    if (lane < 8) {
        float l = g_el[((size_t)p * NN + src) * HH + lane];
        float r = g_er[((size_t)p * NN + dst) * HH + lane];
        float x = l + r;
        x = x > 0.f ? x : 0.2f * x;        // leaky_relu(0.2)
        ex = __expf(x);
        float* dp = g_den + ((size_t)p * NN + dst) * HH + lane;
        asm volatile("red.global.add.f32 [%0], %1;" :: "l"(dp), "f"(ex) : "memory");
    }
    float a = __shfl_sync(0xffffffffu, ex, lane >> 2);   // head h = lane>>2 held by lane h
    const float4* fp = (const float4*)(g_feat + (size_t)src * FTOT + p * HD) + lane * 2;
    float4 v0 = fp[0], v1 = fp[1];
    float* zp = g_z + (size_t)dst * FTOT + p * HD + lane * 8;
    asm volatile("red.global.add.v4.f32 [%0], {%1,%2,%3,%4};"
                 :: "l"(zp), "f"(v0.x * a), "f"(v0.y * a), "f"(v0.z * a), "f"(v0.w * a)
                 : "memory");
    asm volatile("red.global.add.v4.f32 [%0], {%1,%2,%3,%4};"
                 :: "l"(zp + 4), "f"(v1.x * a), "f"(v1.y * a), "f"(v1.z * a), "f"(v1.w * a)
                 : "memory");
}

// ---------------- den -> 1/den (0-degree nodes stay 0: z row is 0 there too) ----------------
__global__ void recip_kernel() {
    int t = blockIdx.x * blockDim.x + threadIdx.x;
    if (t >= PP * NN * HH) return;
    float d = g_den[t];
    g_den[t] = d > 0.f ? __fdividef(1.f, d) : 0.f;
}

// =====================================================================
// GEMM2: out = elu(z * rden) @ sem_w + sem_b.  128x128 tile, 8x8 acc.
// Normalization fused into A-tile load; double-buffered like GEMM1.
// =====================================================================
__global__ __launch_bounds__(256) void gemm_out_kernel(
    const float* __restrict__ semw, const float* __restrict__ semb,
    float* __restrict__ out)
{
    __shared__ float As[16][132];
    __shared__ float Bs[16][128];
    const int tid = threadIdx.x;
    const int tx = tid & 15;
    const int ty = tid >> 4;
    const int rowBase = blockIdx.y * 128;
    const int ar = tid >> 1;
    const int ac = (tid & 1) << 3;
    const int br = tid >> 5;
    const int bc = (tid & 31) << 2;
    const int arow = rowBase + ar;
    const bool aok = arow < NN;
    const float* bpBase = semw + (size_t)br * 128 + bc;

    float acc[8][8];
#pragma unroll
    for (int i = 0; i < 8; i++)
#pragma unroll
        for (int j = 0; j < 8; j++) acc[i][j] = 0.f;

    // A-tile loader (z * 1/den -> elu), 8-aligned base shares one (p,h)
    auto loadA = [&](int base, float4& o0, float4& o1) {
        o0 = make_float4(0.f,0.f,0.f,0.f); o1 = o0;
        if (aok) {
            int p = base >> 8;
            int h = (base >> 5) & 7;
            float rd = g_den[((size_t)p * NN + arow) * HH + h];
            const float* ap = g_z + (size_t)arow * FTOT + base;
            float4 z0 = *(const float4*)ap;
            float4 z1 = *(const float4*)(ap + 4);
            o0 = make_float4(elu_f(z0.x * rd), elu_f(z0.y * rd),
                             elu_f(z0.z * rd), elu_f(z0.w * rd));
            o1 = make_float4(elu_f(z1.x * rd), elu_f(z1.y * rd),
                             elu_f(z1.z * rd), elu_f(z1.w * rd));
        }
    };

    float4 av0, av1;
    loadA(ac, av0, av1);
    float4 bv0 = *(const float4*)bpBase;
    float4 bv1 = *(const float4*)(bpBase + 8 * 128);

    for (int k0 = 0; k0 < FTOT; k0 += 16) {
        As[ac + 0][ar] = av0.x; As[ac + 1][ar] = av0.y;
        As[ac + 2][ar] = av0.z; As[ac + 3][ar] = av0.w;
        As[ac + 4][ar] = av1.x; As[ac + 5][ar] = av1.y;
        As[ac + 6][ar] = av1.z; As[ac + 7][ar] = av1.w;
        *(float4*)&Bs[br][bc]     = bv0;
        *(float4*)&Bs[br + 8][bc] = bv1;
        __syncthreads();

        if (k0 + 16 < FTOT) {
            loadA(k0 + 16 + ac, av0, av1);
            bv0 = *(const float4*)(bpBase + (size_t)(k0 + 16) * 128);
            bv1 = *(const float4*)(bpBase + (size_t)(k0 + 24) * 128);
        }
#pragma unroll
        for (int k = 0; k < 16; k++) {
            float4 a0 = *(const float4*)&As[k][ty << 2];
            float4 a1 = *(const float4*)&As[k][(ty << 2) + 64];
            float4 b0 = *(const float4*)&Bs[k][tx << 2];
            float4 b1 = *(const float4*)&Bs[k][(tx << 2) + 64];
            float a[8] = {a0.x, a0.y, a0.z, a0.w, a1.x, a1.y, a1.z, a1.w};
            float b[8] = {b0.x, b0.y, b0.z, b0.w, b1.x, b1.y, b1.z, b1.w};
#pragma unroll
            for (int i = 0; i < 8; i++)
#pragma unroll
                for (int j = 0; j < 8; j++) acc[i][j] += a[i] * b[j];
        }
        __syncthreads();
    }
#pragma unroll
    for (int qi = 0; qi < 2; qi++)
#pragma unroll
    for (int i = 0; i < 4; i++) {
        int row = rowBase + (ty << 2) + qi * 64 + i;
        if (row < NN) {
            int c0 = tx << 2;
            float4 bb0 = *(const float4*)(semb + c0);
            float4 bb1 = *(const float4*)(semb + c0 + 64);
            float* op = out + (size_t)row * 128;
            *(float4*)(op + c0) =
                make_float4(acc[qi*4+i][0] + bb0.x, acc[qi*4+i][1] + bb0.y,
                            acc[qi*4+i][2] + bb0.z, acc[qi*4+i][3] + bb0.w);
            *(float4*)(op + c0 + 64) =
                make_float4(acc[qi*4+i][4] + bb1.x, acc[qi*4+i][5] + bb1.y,
                            acc[qi*4+i][6] + bb1.z, acc[qi*4+i][7] + bb1.w);
        }
    }
}

// ---------------- launch ----------------
extern "C" void kernel_launch(void* const* d_in, const int* in_sizes, int n_in,
                              void* d_out, int out_size)
{
    const float* h    = (const float*)d_in[0];
    const int*   ei   = (const int*)  d_in[1];
    const float* fcw  = (const float*)d_in[2];
    const float* al   = (const float*)d_in[3];
    const float* arr  = (const float*)d_in[4];
    const float* semw = (const float*)d_in[5];
    const float* semb = (const float*)d_in[6];
    float* out = (float*)d_out;

    init_kernel<<<(NN * FTOT / 4 + 255) / 256, 256>>>();

    dim3 g1(FTOT / 128, (NN + 127) / 128);
    gemm_feat_kernel<<<g1, 256>>>(h, fcw);

    elr_kernel<<<(NN * PP * 32 + 255) / 256, 256>>>(al, arr);

    edge_fused_kernel<<<((size_t)PP * EE * 32 + 255) / 256, 256>>>(ei);

    recip_kernel<<<(PP * NN * HH + 255) / 256, 256>>>();

    dim3 g2(1, (NN + 127) / 128);
    gemm_out_kernel<<<g2, 256>>>(semw, semb, out);
}